// round 6
// baseline (speedup 1.0000x reference)
#include <cuda_runtime.h>
#include <cstdint>

#define BB 1024
#define LL 512
#define TT 50
#define TSTART 48
#define TSTOP 49
#define LOG2E 1.4426950408889634f
#define LN2F  0.6931471805599453f

typedef unsigned long long ull;

__device__ __forceinline__ float ex2f(float x){
    float r; asm("ex2.approx.ftz.f32 %0, %1;" : "=f"(r) : "f"(x)); return r;
}
__device__ __forceinline__ ull pack2(float x, float y){
    ull r; asm("mov.b64 %0, {%1,%2};" : "=l"(r) : "f"(x), "f"(y)); return r;
}
__device__ __forceinline__ void unpack2(ull v, float &x, float &y){
    asm("mov.b64 {%0,%1}, %2;" : "=f"(x), "=f"(y) : "l"(v));
}
__device__ __forceinline__ void ffma2(ull &d, ull a, ull b){
    asm("fma.rn.f32x2 %0, %1, %2, %0;" : "+l"(d) : "l"(a), "l"(b));
}
__device__ __forceinline__ ull add2(ull a, ull b){
    ull r; asm("add.rn.f32x2 %0, %1, %2;" : "=l"(r) : "l"(a), "l"(b)); return r;
}
// warp max of NONNEGATIVE floats via u32 redux (bit pattern order-isomorphic for x>=0)
__device__ __forceinline__ uint32_t redux_max_bits(float x){
    uint32_t r; asm("redux.sync.max.u32 %0, %1, 0xffffffff;" : "=r"(r) : "r"(__float_as_uint(x))); return r;
}
__device__ __forceinline__ uint32_t saddr(const void* p){
    return (uint32_t)__cvta_generic_to_shared(p);
}
__device__ __forceinline__ void cp8(uint32_t dst, const float* src){
    asm volatile("cp.async.ca.shared.global [%0], [%1], 8;" :: "r"(dst), "l"(src));
}
__device__ __forceinline__ void cp_commit(){ asm volatile("cp.async.commit_group;"); }
__device__ __forceinline__ void cp_wait5(){ asm volatile("cp.async.wait_group 5;"); }
__device__ __forceinline__ void cp_wait6(){ asm volatile("cp.async.wait_group 6;"); }

__global__ void zero_out(float* o){ if (threadIdx.x == 0) o[0] = 0.f; }

__global__ void __launch_bounds__(128)
crf_fwd(const float* __restrict__ logits,
        const float* __restrict__ trans,
        const int*   __restrict__ labels,
        const int*   __restrict__ lens,
        float* __restrict__ out)
{
    __shared__ float ring[4][8][64];   // per-warp 8-deep logits-row ring
    __shared__ float vbuf[4][2][64];   // per-warp double-buffered vector broadcast
    __shared__ float xsh[2][64];       // fwd warp's final vector, per pair
    __shared__ float offsh[2];         // fwd warp's renorm offset, per pair

    const int warp  = threadIdx.x >> 5;
    const int lane  = threadIdx.x & 31;
    const int pairI = warp >> 1;
    const int isB   = warp & 1;                 // 0 = forward, 1 = backward
    const int b     = blockIdx.x * 2 + pairI;

    const int j0 = lane;
    const int j1 = lane + 32;
    const bool hasJ1 = (j1 < TT);

    // zero broadcast buffers; tail slots (>=50) must stay 0 forever
    vbuf[warp][0][lane] = 0.f; vbuf[warp][0][lane+32] = 0.f;
    vbuf[warp][1][lane] = 0.f; vbuf[warp][1][lane+32] = 0.f;

    // M rows for this warp's direction: fwd M=E, bwd M=E^T (E = exp(trans))
    ull E0[26], E1[26];
#pragma unroll
    for (int p = 0; p < 25; p++){
        int k0 = 2*p, k1 = 2*p + 1;
        float e00, e01, e10 = 0.f, e11 = 0.f;
        if (!isB){
            e00 = __ldg(&trans[j0*TT + k0]); e01 = __ldg(&trans[j0*TT + k1]);
            if (hasJ1){ e10 = __ldg(&trans[j1*TT + k0]); e11 = __ldg(&trans[j1*TT + k1]); }
        } else {
            e00 = __ldg(&trans[k0*TT + j0]); e01 = __ldg(&trans[k1*TT + j0]);
            if (hasJ1){ e10 = __ldg(&trans[k0*TT + j1]); e11 = __ldg(&trans[k1*TT + j1]); }
        }
        E0[p] = pack2(ex2f(LOG2E*e00), ex2f(LOG2E*e01));
        E1[p] = hasJ1 ? pack2(ex2f(LOG2E*e10), ex2f(LOG2E*e11)) : 0ull;
    }
    E0[25] = 0ull; E1[25] = 0ull;

    const int len   = __ldg(&lens[b]);
    const int h     = len >> 1;
    const int steps = isB ? (len - h) : h;       // bwd steps >= 1 always
    // ring row index for prefetch slot q (bwd fetches one row past its last step: row h-1)
    const int maxq  = isB ? ((h > 0) ? steps : steps - 1)
                          : ((steps > 0) ? steps - 1 : 0);
    const float* __restrict__ rowp   = logits + (long long)b * LL * TT;
    const int*   __restrict__ labrow = labels + (long long)b * LL;

#define TROW(q) (isB ? (len - 1 - (((q) < maxq) ? (q) : maxq)) : (((q) < maxq) ? (q) : maxq))

    // prologue: prefetch ring slots 0..6
#pragma unroll
    for (int q = 0; q < 7; q++){
        int trow = TROW(q);
        if (lane < 25)
            cp8(saddr(&ring[warp][q][0]) + lane*8u, rowp + (long long)trow*TT + lane*2);
        cp_commit();
    }

    // state m; fwd: m = e_START ; bwd: m = P_{len-1} * u, u = exp(trans[STOP,:])
    float mlo, mhi;
    int off = 0;
    float em = 0.f, tr = 0.f;
    int lcur;
    if (!isB){
        mlo = 0.f; mhi = (j1 == TSTART) ? 1.f : 0.f;
        lcur = TSTART;
    } else {
        float u0 = ex2f(LOG2E * __ldg(&trans[TSTOP*TT + j0]));
        float u1 = hasJ1 ? ex2f(LOG2E * __ldg(&trans[TSTOP*TT + j1])) : 0.f;
        cp_wait6(); __syncwarp();               // slot 0 (row len-1) ready
        float a0 = ring[warp][0][j0];
        float a1 = hasJ1 ? ring[warp][0][j1] : 0.f;
        mlo = u0 * ex2f(LOG2E * a0);
        mhi = hasJ1 ? (u1 * ex2f(LOG2E * a1)) : 0.f;
        lcur = __ldg(&labrow[len - 1]);
        tr   = __ldg(&trans[TSTOP*TT + lcur]);
    }

    int phase = 0;
    for (int i = 0; i < steps; i++){
        const int slot = i & 7;

        float* wb = &vbuf[warp][phase][0];
        wb[j0] = mlo;
        if (hasJ1) wb[j1] = mhi;

        cp_wait5();            // rows up to q=i+1 landed (this thread's groups)
        __syncwarp();          // cross-lane visibility: v publish + ring rows

        // prefetch row for slot q=i+7
        {
            int qn = i + 7;
            int trow = TROW(qn);
            if (lane < 25)
                cp8(saddr(&ring[warp][qn & 7][0]) + lane*8u, rowp + (long long)trow*TT + lane*2);
            cp_commit();
        }

        const float* srow = &ring[warp][slot][0];

        // score accumulation (off the recurrence chain)
        if (!isB){
            int lab = __ldg(&labrow[i]);
            em += srow[lab];
            tr += __ldg(&trans[lab*TT + lcur]);
            lcur = lab;
        } else {
            int t = len - 1 - i;
            em += srow[lcur];
            int lprev = (t > 0) ? __ldg(&labrow[t - 1]) : TSTART;
            tr += __ldg(&trans[lcur*TT + lprev]);
            lcur = lprev;
        }

        // mat-vec r = M m : 52 packed FMAs, 13 LDS.128, 4 accumulator chains
        const ulonglong2* vb2 = (const ulonglong2*)wb;
        ull A0[4] = {0ull,0ull,0ull,0ull};
        ull A1[4] = {0ull,0ull,0ull,0ull};
#pragma unroll
        for (int q = 0; q < 13; q++){
            ulonglong2 z = vb2[q];
            ffma2(A0[(2*q)   & 3], E0[2*q],   z.x);
            ffma2(A1[(2*q)   & 3], E1[2*q],   z.x);
            ffma2(A0[(2*q+1) & 3], E0[2*q+1], z.y);
            ffma2(A1[(2*q+1) & 3], E1[2*q+1], z.y);
        }
        ull t0 = add2(add2(A0[0], A0[1]), add2(A0[2], A0[3]));
        ull t1 = add2(add2(A1[0], A1[1]), add2(A1[2], A1[3]));
        float x, y;
        unpack2(t0, x, y); float s0 = x + y;
        unpack2(t1, x, y); float s1 = x + y;

        // elementwise P multiply: fwd uses row i; bwd uses row t_{i+1} (slot i+1).
        // fwd skips on last step (hand-off as E*...); bwd's "extra" multiply at the
        // last step is by row h-1 — exactly the factor fwd skipped.
        bool last  = (i + 1 == steps);
        bool doMul = isB ? (!last || h > 0) : (!last);
        if (doMul){
            const float* mrow = isB ? &ring[warp][(i+1) & 7][0] : srow;
            float p0 = ex2f(LOG2E * mrow[j0]);
            float p1 = hasJ1 ? ex2f(LOG2E * mrow[j1]) : 0.f;
            mlo = p0 * s0; mhi = p1 * s1;
        } else {
            mlo = s0; mhi = s1;
        }

        // exact power-of-2 renorm every 4 steps
        if ((i & 3) == 3){
            uint32_t mb = redux_max_bits(fmaxf(mlo, mhi));
            int k = (int)(mb >> 23) - 127;
            k = max(k, -126);
            off += k;
            float sc = __int_as_float((127 - k) << 23);
            mlo *= sc; mhi *= sc;
        }
        phase ^= 1;
    }

    // pair combine: fwd publishes x and off; bwd computes dot + partition
    if (!isB){
        xsh[pairI][j0] = mlo;
        if (hasJ1) xsh[pairI][j1] = mhi;
        if (lane == 0) offsh[pairI] = (float)off;
    }
    asm volatile("bar.sync %0, %1;" :: "r"(1 + pairI), "r"(64) : "memory");

    if (!isB){
        if (lane == 0 && steps > 0)
            atomicAdd(out, -(em + tr) * (1.0f / BB));
    } else {
        float dx0 = xsh[pairI][j0];
        float dx1 = hasJ1 ? xsh[pairI][j1] : 0.f;
        float s = mlo * dx0 + mhi * dx1;
#pragma unroll
        for (int o = 16; o; o >>= 1) s += __shfl_xor_sync(0xffffffffu, s, o);
        if (lane == 0){
            float part = LN2F * ((float)off + offsh[pairI] + log2f(s));
            atomicAdd(out, (part - em - tr) * (1.0f / BB));
        }
    }
#undef TROW
}

extern "C" void kernel_launch(void* const* d_in, const int* in_sizes, int n_in,
                              void* d_out, int out_size)
{
    const float* logits = (const float*)d_in[0];
    const float* trans  = (const float*)d_in[1];
    const int*   labels = (const int*)d_in[2];
    const int*   lens   = (const int*)d_in[3];
    float* out = (float*)d_out;
    zero_out<<<1, 32>>>(out);
    crf_fwd<<<BB / 2, 128>>>(logits, trans, labels, lens, out);
}

// round 7
// speedup vs baseline: 1.5658x; 1.5658x over previous
#include <cuda_runtime.h>
#include <cstdint>

#define BB 1024
#define LL 512
#define TT 50
#define TSTART 48
#define TSTOP 49
#define LOG2E 1.4426950408889634f
#define LN2F  0.6931471805599453f

typedef unsigned long long ull;
typedef long long ll;

__device__ __forceinline__ float ex2f(float x){
    float r; asm("ex2.approx.ftz.f32 %0, %1;" : "=f"(r) : "f"(x)); return r;
}
__device__ __forceinline__ ull pack2(float x, float y){
    ull r; asm("mov.b64 %0, {%1,%2};" : "=l"(r) : "f"(x), "f"(y)); return r;
}
__device__ __forceinline__ void unpack2(ull v, float &x, float &y){
    asm("mov.b64 {%0,%1}, %2;" : "=f"(x), "=f"(y) : "l"(v));
}
__device__ __forceinline__ void ffma2(ull &d, ull a, ull b){
    asm("fma.rn.f32x2 %0, %1, %2, %0;" : "+l"(d) : "l"(a), "l"(b));
}
__device__ __forceinline__ ull add2(ull a, ull b){
    ull r; asm("add.rn.f32x2 %0, %1, %2;" : "=l"(r) : "l"(a), "l"(b)); return r;
}
// warp max of NONNEGATIVE floats via u32 redux (bit pattern order-isomorphic for x>=0)
__device__ __forceinline__ uint32_t redux_max_bits(float x){
    uint32_t r; asm("redux.sync.max.u32 %0, %1, 0xffffffff;" : "=r"(r) : "r"(__float_as_uint(x))); return r;
}
__device__ __forceinline__ uint32_t saddr(const void* p){
    return (uint32_t)__cvta_generic_to_shared(p);
}
__device__ __forceinline__ void cp8(uint32_t dst, const float* src){
    asm volatile("cp.async.ca.shared.global [%0], [%1], 8;" :: "r"(dst), "l"(src));
}
__device__ __forceinline__ void cp_commit(){ asm volatile("cp.async.commit_group;"); }
__device__ __forceinline__ void cp_wait5(){ asm volatile("cp.async.wait_group 5;"); }
__device__ __forceinline__ void cp_wait6(){ asm volatile("cp.async.wait_group 6;"); }

// 50x50 mat-vec: 52 packed FMAs from 13 LDS.128, 4 accumulator chains
__device__ __forceinline__ void matvec50(const float* wb, const ull* E0, const ull* E1,
                                         float &s0, float &s1){
    const ulonglong2* vb2 = (const ulonglong2*)wb;
    ull A0[4] = {0ull,0ull,0ull,0ull};
    ull A1[4] = {0ull,0ull,0ull,0ull};
#pragma unroll
    for (int q = 0; q < 13; q++){
        ulonglong2 z = vb2[q];
        ffma2(A0[(2*q)   & 3], E0[2*q],   z.x);
        ffma2(A1[(2*q)   & 3], E1[2*q],   z.x);
        ffma2(A0[(2*q+1) & 3], E0[2*q+1], z.y);
        ffma2(A1[(2*q+1) & 3], E1[2*q+1], z.y);
    }
    ull t0 = add2(add2(A0[0], A0[1]), add2(A0[2], A0[3]));
    ull t1 = add2(add2(A1[0], A1[1]), add2(A1[2], A1[3]));
    float x, y;
    unpack2(t0, x, y); s0 = x + y;
    unpack2(t1, x, y); s1 = x + y;
}

__global__ void zero_out(float* o){ if (threadIdx.x == 0) o[0] = 0.f; }

__global__ void __launch_bounds__(128)
crf_fwd(const float* __restrict__ logits,
        const float* __restrict__ trans,
        const int*   __restrict__ labels,
        const int*   __restrict__ lens,
        float* __restrict__ out)
{
    __shared__ float ring[4][8][64];   // per-warp 8-deep logits-row ring
    __shared__ float vbuf[4][2][64];   // per-warp double-buffered vector broadcast
    __shared__ float xsh[2][64];       // fwd warp's final vector, per pair
    __shared__ float offsh[2];         // fwd warp's renorm offset, per pair

    const int warp  = threadIdx.x >> 5;
    const int lane  = threadIdx.x & 31;
    const int pairI = warp >> 1;
    const int isB   = warp & 1;                 // 0 = forward, 1 = backward
    const int b     = blockIdx.x * 2 + pairI;

    const int j0 = lane;
    const int j1 = lane + 32;
    const bool hasJ1 = (j1 < TT);

    const int len = __ldg(&lens[b]);
    const int h   = len >> 1;
    const float* __restrict__ rowp   = logits + (ll)b * LL * TT;
    const int*   __restrict__ labrow = labels + (ll)b * LL;

    // ring row for slot q: fwd rows 0..maxq ascending; bwd rows len-1..len-1-maxq descending
    const int maxq = isB ? (len - 1 - h) : ((h > 0) ? h - 1 : 0);
#define TROW(q) ({ int _mq = min((q), maxq); isB ? (len - 1 - _mq) : _mq; })

    // ---- ring prologue FIRST: slots 0..6 in flight while we do everything else
#pragma unroll
    for (int q = 0; q < 7; q++){
        int trow = TROW(q);
        if (lane < 25)
            cp8(saddr(&ring[warp][q][0]) + lane*8u, rowp + (ll)trow*TT + lane*2);
        cp_commit();
    }

    // zero broadcast buffers; tail slots (>=50) must stay 0 forever
    vbuf[warp][0][lane] = 0.f; vbuf[warp][0][lane+32] = 0.f;
    vbuf[warp][1][lane] = 0.f; vbuf[warp][1][lane+32] = 0.f;

    // M rows for this warp's direction: fwd M=E, bwd M=E^T (E = exp(trans))
    ull E0[26], E1[26];
#pragma unroll
    for (int p = 0; p < 25; p++){
        int k0 = 2*p, k1 = 2*p + 1;
        float e00, e01, e10 = 0.f, e11 = 0.f;
        if (!isB){
            e00 = __ldg(&trans[j0*TT + k0]); e01 = __ldg(&trans[j0*TT + k1]);
            if (hasJ1){ e10 = __ldg(&trans[j1*TT + k0]); e11 = __ldg(&trans[j1*TT + k1]); }
        } else {
            e00 = __ldg(&trans[k0*TT + j0]); e01 = __ldg(&trans[k1*TT + j0]);
            if (hasJ1){ e10 = __ldg(&trans[k0*TT + j1]); e11 = __ldg(&trans[k1*TT + j1]); }
        }
        E0[p] = pack2(ex2f(LOG2E*e00), ex2f(LOG2E*e01));
        E1[p] = hasJ1 ? pack2(ex2f(LOG2E*e10), ex2f(LOG2E*e11)) : 0ull;
    }
    E0[25] = 0ull; E1[25] = 0ull;

    // ---- score phase (lane-parallel gathers; overlaps prologue DRAM latency)
    float em = 0.f, tr = 0.f;
    {
        int ta = isB ? h : 0;
        int tb = isB ? len : h;
#pragma unroll 4
        for (int t = ta + lane; t < tb; t += 32){
            int lab = __ldg(&labrow[t]);
            int prv = (t == 0) ? TSTART : __ldg(&labrow[t - 1]);
            em += __ldg(&rowp[(ll)t*TT + lab]);
            tr += __ldg(&trans[lab*TT + prv]);
        }
        if (isB && lane == 0)
            tr += __ldg(&trans[TSTOP*TT + __ldg(&labrow[len - 1])]);
    }

    // ---- state init
    // fwd: x = e_START, steps = h          (x <- P_t * (E x), t = 0..h-1)
    // bwd: z = P_{len-1} * u, steps = len-h-1 (z <- P_t * (E^T z), t = len-2..h), then bare y = E^T z
    float mlo, mhi;
    int off = 0, steps;
    if (!isB){
        mlo = 0.f; mhi = (j1 == TSTART) ? 1.f : 0.f;
        steps = h;
    } else {
        float u0 = ex2f(LOG2E * __ldg(&trans[TSTOP*TT + j0]));
        float u1 = hasJ1 ? ex2f(LOG2E * __ldg(&trans[TSTOP*TT + j1])) : 0.f;
        cp_wait6(); __syncwarp();               // slot 0 (row len-1) ready
        mlo = u0 * ex2f(LOG2E * ring[warp][0][j0]);
        mhi = hasJ1 ? (u1 * ex2f(LOG2E * ring[warp][0][j1])) : 0.f;
        steps = len - h - 1;
    }
    const int slotOff = isB;    // P-row slot = i + slotOff (fwd: row i; bwd: row len-2-i)

    int phase = 0;
    for (int i = 0; i < steps; i++){
        float* wb = &vbuf[warp][phase][0];
        wb[j0] = mlo;
        if (hasJ1) wb[j1] = mhi;

        cp_wait5();            // slots 0..i+1 landed (this thread's groups)
        __syncwarp();          // cross-lane: v publish + ring rows visible

        {   // prefetch slot q = i+7
            int qn = i + 7;
            int trow = TROW(qn);
            if (lane < 25)
                cp8(saddr(&ring[warp][qn & 7][0]) + lane*8u, rowp + (ll)trow*TT + lane*2);
            cp_commit();
        }

        const float* srow = &ring[warp][(i + slotOff) & 7][0];
        float p0 = ex2f(LOG2E * srow[j0]);                       // off-chain vs matvec
        float p1 = hasJ1 ? ex2f(LOG2E * srow[j1]) : 0.f;

        float s0, s1;
        matvec50(wb, E0, E1, s0, s1);

        mlo = p0 * s0;
        mhi = hasJ1 ? (p1 * s1) : 0.f;

        if ((i & 3) == 3){     // exact power-of-2 renorm
            uint32_t mb = redux_max_bits(fmaxf(mlo, mhi));
            int k = (int)(mb >> 23) - 127;
            k = max(k, -126);
            off += k;
            float sc = __int_as_float((127 - k) << 23);
            mlo *= sc; mhi *= sc;
        }
        phase ^= 1;
    }

    if (isB){   // epilogue: bare y = E^T z
        float* wb = &vbuf[warp][phase][0];
        wb[j0] = mlo;
        if (hasJ1) wb[j1] = mhi;
        __syncwarp();
        float s0, s1;
        matvec50(wb, E0, E1, s0, s1);
        mlo = s0; mhi = s1;
    }

    // ---- pair combine
    if (!isB){
        xsh[pairI][j0] = mlo;
        if (hasJ1) xsh[pairI][j1] = mhi;
        if (lane == 0) offsh[pairI] = (float)off;
    }
    asm volatile("bar.sync %0, %1;" :: "r"(1 + pairI), "r"(64) : "memory");

    // score reduce (both warps)
    float sc = em + tr;
#pragma unroll
    for (int o = 16; o; o >>= 1) sc += __shfl_xor_sync(0xffffffffu, sc, o);

    if (!isB){
        if (lane == 0) atomicAdd(out, -sc * (1.0f / BB));
    } else {
        float dx0 = xsh[pairI][j0];
        float dx1 = hasJ1 ? xsh[pairI][j1] : 0.f;
        float s = mlo * dx0 + mhi * dx1;
#pragma unroll
        for (int o = 16; o; o >>= 1) s += __shfl_xor_sync(0xffffffffu, s, o);
        if (lane == 0){
            float part = LN2F * ((float)off + offsh[pairI] + log2f(s));
            atomicAdd(out, (part - sc) * (1.0f / BB));
        }
    }
#undef TROW
}

extern "C" void kernel_launch(void* const* d_in, const int* in_sizes, int n_in,
                              void* d_out, int out_size)
{
    const float* logits = (const float*)d_in[0];
    const float* trans  = (const float*)d_in[1];
    const int*   labels = (const int*)d_in[2];
    const int*   lens   = (const int*)d_in[3];
    float* out = (float*)d_out;
    zero_out<<<1, 32>>>(out);
    crf_fwd<<<BB / 2, 128>>>(logits, trans, labels, lens, out);
}

// round 9
// speedup vs baseline: 2.1573x; 1.3778x over previous
#include <cuda_runtime.h>
#include <cstdint>

#define BB 1024
#define LL 512
#define TT 50
#define TSTART 48
#define TSTOP 49
#define LOG2E 1.4426950408889634f
#define LN2F  0.6931471805599453f

typedef unsigned long long ull;
typedef long long ll;

__device__ int g_perm[BB];

__device__ __forceinline__ float ex2f(float x){
    float r; asm("ex2.approx.ftz.f32 %0, %1;" : "=f"(r) : "f"(x)); return r;
}
__device__ __forceinline__ ull pack2(float x, float y){
    ull r; asm("mov.b64 %0, {%1,%2};" : "=l"(r) : "f"(x), "f"(y)); return r;
}
__device__ __forceinline__ void unpack2(ull v, float &x, float &y){
    asm("mov.b64 {%0,%1}, %2;" : "=f"(x), "=f"(y) : "l"(v));
}
__device__ __forceinline__ void ffma2(ull &d, ull a, ull b){
    asm("fma.rn.f32x2 %0, %1, %2, %0;" : "+l"(d) : "l"(a), "l"(b));
}
__device__ __forceinline__ ull add2(ull a, ull b){
    ull r; asm("add.rn.f32x2 %0, %1, %2;" : "=l"(r) : "l"(a), "l"(b)); return r;
}
// warp max of NONNEGATIVE floats via u32 redux (bit pattern order-isomorphic for x>=0)
__device__ __forceinline__ uint32_t redux_max_bits(float x){
    uint32_t r; asm("redux.sync.max.u32 %0, %1, 0xffffffff;" : "=r"(r) : "r"(__float_as_uint(x))); return r;
}
__device__ __forceinline__ uint32_t saddr(const void* p){
    return (uint32_t)__cvta_generic_to_shared(p);
}
__device__ __forceinline__ void cp8(uint32_t dst, const float* src){
    asm volatile("cp.async.ca.shared.global [%0], [%1], 8;" :: "r"(dst), "l"(src));
}
__device__ __forceinline__ void cp_commit(){ asm volatile("cp.async.commit_group;"); }
__device__ __forceinline__ void cp_wait5(){ asm volatile("cp.async.wait_group 5;"); }
__device__ __forceinline__ void cp_wait6(){ asm volatile("cp.async.wait_group 6;"); }

// 50x50 mat-vec: 52 packed FMAs from 13 LDS.128, 4 accumulator chains
__device__ __forceinline__ void matvec50(const float* wb, const ull* E0, const ull* E1,
                                         float &s0, float &s1){
    const ulonglong2* vb2 = (const ulonglong2*)wb;
    ull A0[4] = {0ull,0ull,0ull,0ull};
    ull A1[4] = {0ull,0ull,0ull,0ull};
#pragma unroll
    for (int q = 0; q < 13; q++){
        ulonglong2 z = vb2[q];
        ffma2(A0[(2*q)   & 3], E0[2*q],   z.x);
        ffma2(A1[(2*q)   & 3], E1[2*q],   z.x);
        ffma2(A0[(2*q+1) & 3], E0[2*q+1], z.y);
        ffma2(A1[(2*q+1) & 3], E1[2*q+1], z.y);
    }
    ull t0 = add2(add2(A0[0], A0[1]), add2(A0[2], A0[3]));
    ull t1 = add2(add2(A1[0], A1[1]), add2(A1[2], A1[3]));
    float x, y;
    unpack2(t0, x, y); s0 = x + y;
    unpack2(t1, x, y); s1 = x + y;
}

__global__ void zero_out(float* o){ if (threadIdx.x == 0) o[0] = 0.f; }

// Longest-first schedule: counting sort of batch indices by len (descending).
__global__ void __launch_bounds__(512) sched(const int* __restrict__ lens){
    __shared__ int hist[512];
    __shared__ int base[512];
    const int tid = threadIdx.x;
    hist[tid] = 0;
    __syncthreads();
    // bin = 512 - len  (len in [1,512] -> bin in [0,511]); bin 0 = longest
    for (int i = tid; i < BB; i += 512)
        atomicAdd(&hist[LL - __ldg(&lens[i])], 1);
    __syncthreads();
    int cnt = hist[tid];
    // Hillis-Steele inclusive scan over 512 bins
    for (int o = 1; o < 512; o <<= 1){
        int v = (tid >= o) ? hist[tid - o] : 0;
        __syncthreads();
        hist[tid] += v;
        __syncthreads();
    }
    base[tid] = hist[tid] - cnt;            // exclusive prefix
    __syncthreads();
    for (int i = tid; i < BB; i += 512){
        int bin = LL - __ldg(&lens[i]);
        int pos = atomicAdd(&base[bin], 1);
        g_perm[pos] = i;
    }
}

__global__ void __launch_bounds__(128)
crf_fwd(const float* __restrict__ logits,
        const float* __restrict__ trans,
        const int*   __restrict__ labels,
        const int*   __restrict__ lens,
        float* __restrict__ out)
{
    __shared__ float ring[4][8][64];   // per-warp 8-deep logits-row ring
    __shared__ float vbuf[4][2][64];   // per-warp double-buffered vector broadcast
    __shared__ float xsh[2][64];       // fwd warp's final vector, per pair
    __shared__ float offsh[2];         // fwd warp's renorm offset, per pair

    const int warp  = threadIdx.x >> 5;
    const int lane  = threadIdx.x & 31;
    const int pairI = warp >> 1;
    const int isB   = warp & 1;                 // 0 = forward, 1 = backward
    const int b     = g_perm[blockIdx.x * 2 + pairI];   // length-sorted schedule

    const int j0 = lane;
    const int j1 = lane + 32;
    const bool hasJ1 = (j1 < TT);

    const int len = __ldg(&lens[b]);
    const int h   = len >> 1;
    const float* __restrict__ rowp   = logits + (ll)b * LL * TT;
    const int*   __restrict__ labrow = labels + (ll)b * LL;

    // ring row for slot q: fwd rows 0..maxq ascending; bwd rows len-1..len-1-maxq descending
    const int maxq = isB ? (len - 1 - h) : ((h > 0) ? h - 1 : 0);
#define TROW(q) ({ int _mq = min((q), maxq); isB ? (len - 1 - _mq) : _mq; })

    // ---- ring prologue FIRST: slots 0..6 in flight while we do everything else
#pragma unroll
    for (int q = 0; q < 7; q++){
        int trow = TROW(q);
        if (lane < 25)
            cp8(saddr(&ring[warp][q][0]) + lane*8u, rowp + (ll)trow*TT + lane*2);
        cp_commit();
    }

    // zero broadcast buffers; tail slots (>=50) must stay 0 forever
    vbuf[warp][0][lane] = 0.f; vbuf[warp][0][lane+32] = 0.f;
    vbuf[warp][1][lane] = 0.f; vbuf[warp][1][lane+32] = 0.f;

    // M rows for this warp's direction: fwd M=E, bwd M=E^T (E = exp(trans))
    ull E0[26], E1[26];
#pragma unroll
    for (int p = 0; p < 25; p++){
        int k0 = 2*p, k1 = 2*p + 1;
        float e00, e01, e10 = 0.f, e11 = 0.f;
        if (!isB){
            e00 = __ldg(&trans[j0*TT + k0]); e01 = __ldg(&trans[j0*TT + k1]);
            if (hasJ1){ e10 = __ldg(&trans[j1*TT + k0]); e11 = __ldg(&trans[j1*TT + k1]); }
        } else {
            e00 = __ldg(&trans[k0*TT + j0]); e01 = __ldg(&trans[k1*TT + j0]);
            if (hasJ1){ e10 = __ldg(&trans[k0*TT + j1]); e11 = __ldg(&trans[k1*TT + j1]); }
        }
        E0[p] = pack2(ex2f(LOG2E*e00), ex2f(LOG2E*e01));
        E1[p] = hasJ1 ? pack2(ex2f(LOG2E*e10), ex2f(LOG2E*e11)) : 0ull;
    }
    E0[25] = 0ull; E1[25] = 0ull;

    // ---- score phase (lane-parallel gathers; overlaps prologue DRAM latency)
    float em = 0.f, tr = 0.f;
    {
        int ta = isB ? h : 0;
        int tb = isB ? len : h;
#pragma unroll 4
        for (int t = ta + lane; t < tb; t += 32){
            int lab = __ldg(&labrow[t]);
            int prv = (t == 0) ? TSTART : __ldg(&labrow[t - 1]);
            em += __ldg(&rowp[(ll)t*TT + lab]);
            tr += __ldg(&trans[lab*TT + prv]);
        }
        if (isB && lane == 0)
            tr += __ldg(&trans[TSTOP*TT + __ldg(&labrow[len - 1])]);
    }

    // ---- state init
    // fwd: x = e_START, steps = h            (x <- P_t * (E x), t = 0..h-1)
    // bwd: z = P_{len-1} * u, steps = len-h-1 (z <- P_t * (E^T z), t = len-2..h), then bare y = E^T z
    float mlo, mhi;
    int off = 0, steps;
    if (!isB){
        mlo = 0.f; mhi = (j1 == TSTART) ? 1.f : 0.f;
        steps = h;
    } else {
        float u0 = ex2f(LOG2E * __ldg(&trans[TSTOP*TT + j0]));
        float u1 = hasJ1 ? ex2f(LOG2E * __ldg(&trans[TSTOP*TT + j1])) : 0.f;
        cp_wait6(); __syncwarp();               // slot 0 (row len-1) ready
        mlo = u0 * ex2f(LOG2E * ring[warp][0][j0]);
        mhi = hasJ1 ? (u1 * ex2f(LOG2E * ring[warp][0][j1])) : 0.f;
        steps = len - h - 1;
    }
    const int slotOff = isB;    // P-row slot = i + slotOff (fwd: row i; bwd: row len-2-i)

    int phase = 0;
    for (int i = 0; i < steps; i++){
        float* wb = &vbuf[warp][phase][0];
        wb[j0] = mlo;
        if (hasJ1) wb[j1] = mhi;

        cp_wait5();            // slots 0..i+1 landed (this thread's groups)
        __syncwarp();          // cross-lane: v publish + ring rows visible

        {   // prefetch slot q = i+7
            int qn = i + 7;
            int trow = TROW(qn);
            if (lane < 25)
                cp8(saddr(&ring[warp][qn & 7][0]) + lane*8u, rowp + (ll)trow*TT + lane*2);
            cp_commit();
        }

        const float* srow = &ring[warp][(i + slotOff) & 7][0];
        float p0 = ex2f(LOG2E * srow[j0]);                       // off-chain vs matvec
        float p1 = hasJ1 ? ex2f(LOG2E * srow[j1]) : 0.f;

        float s0, s1;
        matvec50(wb, E0, E1, s0, s1);

        mlo = p0 * s0;
        mhi = hasJ1 ? (p1 * s1) : 0.f;

        if ((i & 3) == 3){     // exact power-of-2 renorm
            uint32_t mb = redux_max_bits(fmaxf(mlo, mhi));
            int k = (int)(mb >> 23) - 127;
            k = max(k, -126);
            off += k;
            float sc = __int_as_float((127 - k) << 23);
            mlo *= sc; mhi *= sc;
        }
        phase ^= 1;
    }

    if (isB){   // epilogue: bare y = E^T z
        float* wb = &vbuf[warp][phase][0];
        wb[j0] = mlo;
        if (hasJ1) wb[j1] = mhi;
        __syncwarp();
        float s0, s1;
        matvec50(wb, E0, E1, s0, s1);
        mlo = s0; mhi = s1;
    }

    // ---- pair combine
    if (!isB){
        xsh[pairI][j0] = mlo;
        if (hasJ1) xsh[pairI][j1] = mhi;
        if (lane == 0) offsh[pairI] = (float)off;
    }
    asm volatile("bar.sync %0, %1;" :: "r"(1 + pairI), "r"(64) : "memory");

    // score reduce (both warps)
    float sc = em + tr;
#pragma unroll
    for (int o = 16; o; o >>= 1) sc += __shfl_xor_sync(0xffffffffu, sc, o);

    if (!isB){
        if (lane == 0) atomicAdd(out, -sc * (1.0f / BB));
    } else {
        float dx0 = xsh[pairI][j0];
        float dx1 = hasJ1 ? xsh[pairI][j1] : 0.f;
        float s = mlo * dx0 + mhi * dx1;
#pragma unroll
        for (int o = 16; o; o >>= 1) s += __shfl_xor_sync(0xffffffffu, s, o);
        if (lane == 0){
            float part = LN2F * ((float)off + offsh[pairI] + log2f(s));
            atomicAdd(out, (part - sc) * (1.0f / BB));
        }
    }
#undef TROW
}

extern "C" void kernel_launch(void* const* d_in, const int* in_sizes, int n_in,
                              void* d_out, int out_size)
{
    const float* logits = (const float*)d_in[0];
    const float* trans  = (const float*)d_in[1];
    const int*   labels = (const int*)d_in[2];
    const int*   lens   = (const int*)d_in[3];
    float* out = (float*)d_out;
    zero_out<<<1, 32>>>(out);
    sched<<<1, 512>>>(lens);
    crf_fwd<<<BB / 2, 128>>>(logits, trans, labels, lens, out);
}